// round 7
// baseline (speedup 1.0000x reference)
#include <cuda_runtime.h>
#include <math.h>

#define Hh 48
#define Ww 64
#define HW 3072
#define Cc 256
#define HIDDEN 128
#define CTX 64
#define CORR_DIM 324
#define GIN 516
#define NSAMP 37

__constant__ int c_lvlOff[4] = {0, 3072, 3840, 4032};
__constant__ int c_lvlH[4]   = {48, 24, 12, 6};
__constant__ int c_lvlW[4]   = {64, 32, 16, 8};

__constant__ float c_rot[12][3] = {
    {0,0,0},{0,0,0},{0,0,0},{0,0,0},{0,0,0},{0,0,0},
    {1,0,0},{-1,0,0},{0,1,0},{0,-1,0},{0,0,1},{0,0,-1}};
__constant__ float c_trs[12][3] = {
    {1,0,0},{-1,0,0},{0,1,0},{0,-1,0},{0,0,1},{0,0,-1},
    {0,0,0},{0,0,0},{0,0,0},{0,0,0},{0,0,0},{0,0,0}};
__constant__ float c_scales[3] = {0.25f, 1.0f, 4.0f};

__device__ float g_corr[HW * 3072];
__device__ float g_pyr1[HW * 768];
__device__ float g_pyr2[HW * 192];
__device__ float g_pyr3[HW * 48];
__device__ float g_sat0[HW * 3185];
__device__ float g_sat1[HW * 825];
__device__ float g_sat2[HW * 221];
__device__ float g_sat3[HW * 63];
__device__ float g_X[3 * HW];
__device__ float g_K[4];
__device__ float g_samp[NSAMP * 12];
__device__ float g_conf[NSAMP];
__device__ int   g_topi[3];
__device__ float g_wk[3];
__device__ float g_pose[7];
__device__ float g_xin[(CORR_DIM + CTX) * HW];
__device__ float g_h[HIDDEN * HW];
__device__ float g_zg[HIDDEN * HW];
__device__ float g_rgh[HIDDEN * HW];
__device__ float g_feat[HIDDEN];
__device__ float g_pA[3 * HIDDEN * HW];
__device__ float g_pB[3 * HIDDEN * HW];
__device__ float g_wTz[GIN * 128 * 9];
__device__ float g_wTr[GIN * 128 * 9];
__device__ float g_wTq[GIN * 128 * 9];
__device__ float g_wTh[128 * 128 * 9];

// ---- packed fp32x2 helpers (Blackwell dual-rate FP32 path) ----
typedef unsigned long long u64t;
__device__ __forceinline__ u64t pk2(float lo, float hi) {
    u64t r; asm("mov.b64 %0, {%1, %2};" : "=l"(r) : "f"(lo), "f"(hi)); return r;
}
__device__ __forceinline__ void upk2(u64t v, float& lo, float& hi) {
    asm("mov.b64 {%0, %1}, %2;" : "=f"(lo), "=f"(hi) : "l"(v));
}
__device__ __forceinline__ u64t ffma2(u64t a, u64t b, u64t c) {
    u64t d; asm("fma.rn.f32x2 %0, %1, %2, %3;" : "=l"(d) : "l"(a), "l"(b), "l"(c)); return d;
}

__device__ __forceinline__ void qmul_d(const float* a, const float* b, float* o) {
    o[0] = a[0]*b[0] - a[1]*b[1] - a[2]*b[2] - a[3]*b[3];
    o[1] = a[0]*b[1] + a[1]*b[0] + a[2]*b[3] - a[3]*b[2];
    o[2] = a[0]*b[2] - a[1]*b[3] + a[2]*b[0] + a[3]*b[1];
    o[3] = a[0]*b[3] + a[1]*b[2] - a[2]*b[1] + a[3]*b[0];
}
__device__ __forceinline__ void qapply_d(const float* q, const float* v, float* o) {
    float qv[4] = {0.f, v[0], v[1], v[2]};
    float qc[4] = {q[0], -q[1], -q[2], -q[3]};
    float t[4], r[4];
    qmul_d(q, qv, t);
    qmul_d(t, qc, r);
    o[0] = r[1]; o[1] = r[2]; o[2] = r[3];
}

__global__ void k_setup(const float* __restrict__ depth, const float* __restrict__ intr) {
    int p = blockIdx.x * 256 + threadIdx.x;
    float fx = 60.0f + 40.0f * intr[0];
    float fy = 60.0f + 40.0f * intr[1];
    float cx = 32.0f + 4.0f * (intr[2] - 0.5f);
    float cy = 24.0f + 4.0f * (intr[3] - 0.5f);
    if (p == 0) {
        g_K[0] = fx; g_K[1] = fy; g_K[2] = cx; g_K[3] = cy;
        g_pose[0] = 1.f; g_pose[1] = 0.f; g_pose[2] = 0.f; g_pose[3] = 0.f;
        g_pose[4] = 0.f; g_pose[5] = 0.f; g_pose[6] = 0.f;
    }
    if (p < HW) {
        float u = (float)(p % Ww);
        float v = (float)(p / Ww);
        float d = 4.0f + 20.0f * depth[p];
        g_X[p]          = (u - cx) / fx * d;
        g_X[HW + p]     = (v - cy) / fy * d;
        g_X[2 * HW + p] = d;
    }
}

__global__ void k_zeroh() {
    int i = blockIdx.x * 256 + threadIdx.x;
    if (i < HIDDEN * HW) g_h[i] = 0.f;
}

__global__ void k_ctx(const float* __restrict__ ctx) {
    int i = blockIdx.x * 256 + threadIdx.x;
    if (i < CTX * HW) g_xin[CORR_DIM * HW + i] = ctx[i];
}

// corr[i][j] = (1/16) sum_c fd[c][i] * rgb[c][j]
__global__ void k_corr(const float* __restrict__ A, const float* __restrict__ B) {
    __shared__ float As[16][64];
    __shared__ float Bs[16][64];
    int i0 = blockIdx.y * 64;
    int j0 = blockIdx.x * 64;
    int tid = threadIdx.x;
    int tx = tid & 15;
    int ty = tid >> 4;
    float acc[4][4];
#pragma unroll
    for (int r = 0; r < 4; r++)
#pragma unroll
        for (int c = 0; c < 4; c++) acc[r][c] = 0.f;

    for (int k0 = 0; k0 < Cc; k0 += 16) {
        for (int t = tid; t < 1024; t += 256) {
            int kk = t >> 6, ii = t & 63;
            As[kk][ii] = A[(k0 + kk) * HW + i0 + ii];
            Bs[kk][ii] = B[(k0 + kk) * HW + j0 + ii];
        }
        __syncthreads();
#pragma unroll
        for (int kk = 0; kk < 16; kk++) {
            float4 a4 = *(const float4*)&As[kk][ty * 4];
            float4 b4 = *(const float4*)&Bs[kk][tx * 4];
            float a[4] = {a4.x, a4.y, a4.z, a4.w};
            float b[4] = {b4.x, b4.y, b4.z, b4.w};
#pragma unroll
            for (int r = 0; r < 4; r++)
#pragma unroll
                for (int c = 0; c < 4; c++)
                    acc[r][c] = fmaf(a[r], b[c], acc[r][c]);
        }
        __syncthreads();
    }
#pragma unroll
    for (int r = 0; r < 4; r++) {
        float4 o;
        o.x = acc[r][0] * 0.0625f;
        o.y = acc[r][1] * 0.0625f;
        o.z = acc[r][2] * 0.0625f;
        o.w = acc[r][3] * 0.0625f;
        *(float4*)&g_corr[(i0 + ty * 4 + r) * 3072 + j0 + tx * 4] = o;
    }
}

__global__ void k_pool(int level) {
    const float* src; float* dst; int Hs, Ws;
    if (level == 1)      { src = g_corr; dst = g_pyr1; Hs = 48; Ws = 64; }
    else if (level == 2) { src = g_pyr1; dst = g_pyr2; Hs = 24; Ws = 32; }
    else                 { src = g_pyr2; dst = g_pyr3; Hs = 12; Ws = 16; }
    int Hd = Hs >> 1, Wd = Ws >> 1;
    int per = Hd * Wd;
    long idx = (long)blockIdx.x * 256 + threadIdx.x;
    if (idx >= (long)HW * per) return;
    int p = (int)(idx / per), r = (int)(idx % per);
    int hy = r / Wd, wx = r % Wd;
    const float* s = src + (long)p * (Hs * Ws);
    int b = (2 * hy) * Ws + 2 * wx;
    dst[idx] = 0.25f * (s[b] + s[b + 1] + s[b + Ws] + s[b + Ws + 1]);
}

__global__ void k_sat(int level) {
    const float* src; float* dstA; int Hl, Wl;
    if (level == 0)      { src = g_corr; dstA = g_sat0; Hl = 48; Wl = 64; }
    else if (level == 1) { src = g_pyr1; dstA = g_sat1; Hl = 24; Wl = 32; }
    else if (level == 2) { src = g_pyr2; dstA = g_sat2; Hl = 12; Wl = 16; }
    else                 { src = g_pyr3; dstA = g_sat3; Hl = 6;  Wl = 8;  }
    __shared__ float S[3185];
    int p = blockIdx.x;
    int satW = Wl + 1;
    int total = (Hl + 1) * satW;
    const float* s = src + (long)p * (Hl * Wl);
    int t = threadIdx.x;
    for (int c = t; c < satW; c += 128) S[c] = 0.f;
    if (t < Hl) {
        float run = 0.f;
        S[(t + 1) * satW] = 0.f;
        for (int c = 0; c < Wl; c++) {
            run += s[t * Wl + c];
            S[(t + 1) * satW + c + 1] = run;
        }
    }
    __syncthreads();
    if (t >= 1 && t <= Wl) {
        float run = 0.f;
        for (int r = 1; r <= Hl; r++) {
            run += S[r * satW + t];
            S[r * satW + t] = run;
        }
    }
    __syncthreads();
    float* D = dstA + (long)p * total;
    for (int i = t; i < total; i += 128) D[i] = S[i];
}

// W[O][I][9] -> wT[I][O][9]
__global__ void k_wT(const float* __restrict__ w, int which) {
    float* dst; int I;
    if (which == 0)      { dst = g_wTz; I = GIN; }
    else if (which == 1) { dst = g_wTr; I = GIN; }
    else if (which == 2) { dst = g_wTq; I = GIN; }
    else                 { dst = g_wTh; I = 128; }
    int total = 128 * I * 9;
    int idx = blockIdx.x * 256 + threadIdx.x;
    if (idx >= total) return;
    int o = idx / (I * 9);
    int r = idx % (I * 9);
    int i = r / 9, k = r % 9;
    dst[(i * 128 + o) * 9 + k] = w[idx];
}

__global__ void k_sample_prep() {
    int n = threadIdx.x;
    if (n < NSAMP) g_conf[n] = 0.f;
    if (n >= NSAMP) return;
    float qc[4] = {g_pose[0], g_pose[1], g_pose[2], g_pose[3]};
    float tc[3] = {g_pose[4], g_pose[5], g_pose[6]};
    float dq[4], dt[3];
    if (n < 36) {
        int b = n / 3, m = n % 3;
        float sc = c_scales[m];
        float rx = c_rot[b][0], ry = c_rot[b][1], rz = c_rot[b][2];
        float rn = sqrtf(rx * rx + ry * ry + rz * rz);
        float dnm = fmaxf(rn, 1e-8f);
        float ha = 0.02f * sc * 0.5f;
        float sh = sinf(ha);
        dq[0] = cosf(ha);
        dq[1] = rx / dnm * sh;
        dq[2] = ry / dnm * sh;
        dq[3] = rz / dnm * sh;
        float ts = 0.02f * sc;
        dt[0] = c_trs[b][0] * ts;
        dt[1] = c_trs[b][1] * ts;
        dt[2] = c_trs[b][2] * ts;
    } else {
        dq[0] = 1.f; dq[1] = 0.f; dq[2] = 0.f; dq[3] = 0.f;
        dt[0] = 0.f; dt[1] = 0.f; dt[2] = 0.f;
    }
    float q[4];
    qmul_d(qc, dq, q);
    float inv = rsqrtf(q[0]*q[0] + q[1]*q[1] + q[2]*q[2] + q[3]*q[3]);
    q[0] *= inv; q[1] *= inv; q[2] *= inv; q[3] *= inv;
    float rd[3];
    qapply_d(qc, dt, rd);
    float w = q[0], x = q[1], y = q[2], z = q[3];
    float* S = g_samp + n * 12;
    S[0] = 1.f - 2.f * (y * y + z * z);
    S[1] = 2.f * (x * y - w * z);
    S[2] = 2.f * (x * z + w * y);
    S[3] = 2.f * (x * y + w * z);
    S[4] = 1.f - 2.f * (x * x + z * z);
    S[5] = 2.f * (y * z - w * x);
    S[6] = 2.f * (x * z - w * y);
    S[7] = 2.f * (y * z + w * x);
    S[8] = 1.f - 2.f * (x * x + y * y);
    S[9]  = tc[0] + rd[0];
    S[10] = tc[1] + rd[1];
    S[11] = tc[2] + rd[2];
}

__device__ __forceinline__ float satT(const float* S, int Hl, int Wl, int satW, int a, int b) {
    int c0 = min(max(a - 4, 0), Wl);
    int c1 = min(max(a + 5, 0), Wl);
    int r0 = min(max(b - 4, 0), Hl);
    int r1 = min(max(b + 5, 0), Hl);
    return S[r1 * satW + c1] - S[r0 * satW + c1] - S[r1 * satW + c0] + S[r0 * satW + c0];
}

__device__ __forceinline__ float confLevel(const float* S, int Hl, int Wl, int satW,
                                           float ul, float vl) {
    float bx = floorf(ul), by = floorf(vl);
    float fx = ul - bx, fy = vl - by;
    int ax = (int)bx, ay = (int)by;
    float T00 = satT(S, Hl, Wl, satW, ax,     ay);
    float T10 = satT(S, Hl, Wl, satW, ax + 1, ay);
    float T01 = satT(S, Hl, Wl, satW, ax,     ay + 1);
    float T11 = satT(S, Hl, Wl, satW, ax + 1, ay + 1);
    return (1.f - fx) * (1.f - fy) * T00 + fx * (1.f - fy) * T10
         + (1.f - fx) * fy * T01 + fx * fy * T11;
}

__global__ void k_conf() {
    int n = blockIdx.x;
    int chunk = blockIdx.y;           // 0..3, 768 px each
    __shared__ float sR[12];
    __shared__ float red[256];
    int tid = threadIdx.x;
    if (tid < 12) sR[tid] = g_samp[n * 12 + tid];
    __syncthreads();
    float fx = g_K[0], fy = g_K[1], cx = g_K[2], cy = g_K[3];
    float acc = 0.f;
    int p0 = chunk * 768;
    for (int p = p0 + tid; p < p0 + 768; p += 256) {
        float X = g_X[p], Y = g_X[HW + p], Z = g_X[2 * HW + p];
        float xc = sR[0] * X + sR[1] * Y + sR[2] * Z + sR[9];
        float yc = sR[3] * X + sR[4] * Y + sR[5] * Z + sR[10];
        float zc = sR[6] * X + sR[7] * Y + sR[8] * Z + sR[11];
        zc = fmaxf(zc, 0.1f);
        float u = fx * xc / zc + cx;
        float v = fy * yc / zc + cy;
        acc += confLevel(g_sat0 + (long)p * 3185, 48, 64, 65, u,          v);
        acc += confLevel(g_sat1 + (long)p * 825,  24, 32, 33, u * 0.5f,   v * 0.5f);
        acc += confLevel(g_sat2 + (long)p * 221,  12, 16, 17, u * 0.25f,  v * 0.25f);
        acc += confLevel(g_sat3 + (long)p * 63,    6,  8,  9, u * 0.125f, v * 0.125f);
    }
    red[tid] = acc;
    __syncthreads();
    for (int s = 128; s > 0; s >>= 1) {
        if (tid < s) red[tid] += red[tid + s];
        __syncthreads();
    }
    if (tid == 0) atomicAdd(&g_conf[n], red[0]);
}

__global__ void k_topk() {
    if (threadIdx.x != 0) return;
    float v[NSAMP];
    for (int i = 0; i < NSAMP; i++) v[i] = g_conf[i] * (1.0f / 995328.0f);
    float tv[3]; int ti[3];
    for (int k = 0; k < 3; k++) {
        float best = -1e30f; int bi = 0;
        for (int i = 0; i < NSAMP; i++)
            if (v[i] > best) { best = v[i]; bi = i; }
        tv[k] = best; ti[k] = bi;
        v[bi] = -1e30f;
    }
    float m = tv[0];
    float e0 = expf(tv[0] - m), e1 = expf(tv[1] - m), e2 = expf(tv[2] - m);
    float s = e0 + e1 + e2;
    g_topi[0] = ti[0]; g_topi[1] = ti[1]; g_topi[2] = ti[2];
    g_wk[0] = e0 / s; g_wk[1] = e1 / s; g_wk[2] = e2 / s;
}

// fused correlation features for the top-3 samples -> g_xin planes [0,324)
__global__ void k_fused() {
    int p = blockIdx.x;
    __shared__ float sRow[4080];
    __shared__ int   sBx[12], sBy[12];
    __shared__ float sFx[12], sFy[12], sWk[3];
    int tid = threadIdx.x;
    {
        const float* r0 = g_corr + (long)p * 3072;
        for (int i = tid; i < 3072; i += 128) sRow[i] = r0[i];
        const float* r1 = g_pyr1 + (long)p * 768;
        for (int i = tid; i < 768; i += 128) sRow[3072 + i] = r1[i];
        const float* r2 = g_pyr2 + (long)p * 192;
        for (int i = tid; i < 192; i += 128) sRow[3840 + i] = r2[i];
        const float* r3 = g_pyr3 + (long)p * 48;
        if (tid < 48) sRow[4032 + tid] = r3[tid];
    }
    if (tid < 3) {
        int n = g_topi[tid];
        sWk[tid] = g_wk[tid];
        const float* S = g_samp + n * 12;
        float X = g_X[p], Y = g_X[HW + p], Z = g_X[2 * HW + p];
        float xc = S[0] * X + S[1] * Y + S[2] * Z + S[9];
        float yc = S[3] * X + S[4] * Y + S[5] * Z + S[10];
        float zc = S[6] * X + S[7] * Y + S[8] * Z + S[11];
        zc = fmaxf(zc, 0.1f);
        float u = g_K[0] * xc / zc + g_K[2];
        float v = g_K[1] * yc / zc + g_K[3];
        float inv = 1.f;
        for (int l = 0; l < 4; l++) {
            float ul = u * inv, vl = v * inv;
            float bx = floorf(ul), by = floorf(vl);
            sBx[tid * 4 + l] = (int)bx;
            sBy[tid * 4 + l] = (int)by;
            sFx[tid * 4 + l] = ul - bx;
            sFy[tid * 4 + l] = vl - by;
            inv *= 0.5f;
        }
    }
    __syncthreads();
    for (int c = tid; c < CORR_DIM; c += 128) {
        int l = c / 81, o = c % 81;
        int oy = o / 9 - 4, ox = o % 9 - 4;
        const float* row = sRow + c_lvlOff[l];
        int Hl = c_lvlH[l], Wl = c_lvlW[l];
        float acc = 0.f;
#pragma unroll
        for (int k = 0; k < 3; k++) {
            int i = k * 4 + l;
            int x0 = sBx[i] + ox, y0 = sBy[i] + oy;
            float fxw = sFx[i], fyw = sFy[i];
            float s = 0.f;
            bool vx0 = (x0 >= 0 && x0 < Wl);
            bool vx1 = (x0 + 1 >= 0 && x0 + 1 < Wl);
            bool vy0 = (y0 >= 0 && y0 < Hl);
            bool vy1 = (y0 + 1 >= 0 && y0 + 1 < Hl);
            if (vx0 && vy0) s += (1.f - fxw) * (1.f - fyw) * row[y0 * Wl + x0];
            if (vx1 && vy0) s += fxw * (1.f - fyw) * row[y0 * Wl + x0 + 1];
            if (vx0 && vy1) s += (1.f - fxw) * fyw * row[(y0 + 1) * Wl + x0];
            if (vx1 && vy1) s += fxw * fyw * row[(y0 + 1) * Wl + x0 + 1];
            acc += sWk[k] * s;
        }
        g_xin[c * HW + p] = acc;
    }
}

// ---------------------------------------------------------------------------
// Conv v3: implicit GEMM with packed fp32x2 (FFMA2) math.
// Tile 64 oc x 128 px (2 rows), splitK=3, double-buffered smem, weights
// staged DUPLICATED as float2(w,w) so a broadcast LDS.64 yields the packed
// operand. Output px paired (x, x+1) shares taps via overlapping vin pairs.
// ---------------------------------------------------------------------------
__global__ void __launch_bounds__(256, 1) k_conv2(int mode) {
    const float* inA; const float* inB; const float* wT; float* outP; int C;
    if (mode == 0)      { inA = g_h;   inB = g_xin; wT = g_wTz; outP = g_pA; C = GIN; }
    else if (mode == 1) { inA = g_h;   inB = g_xin; wT = g_wTr; outP = g_pB; C = GIN; }
    else if (mode == 2) { inA = g_rgh; inB = g_xin; wT = g_wTq; outP = g_pA; C = GIN; }
    else                { inA = g_h;   inB = g_h;   wT = g_wTh; outP = g_pB; C = 128; }

    const int y0 = blockIdx.y * 2;
    const int ocBase = blockIdx.x * 64;
    const int kz = blockIdx.z;
    const int c0 = kz * C / 3;
    const int c1 = (kz + 1) * C / 3;
    outP += kz * HIDDEN * HW;

    const int tid = threadIdx.x;
    const int pxg = tid & 31;
    const int ocg = tid >> 5;
    const int r  = pxg >> 4;          // 0..1 output row within tile
    const int x4 = (pxg & 15) * 4;    // 0,4,...,60

    __shared__ float  sIn[2][4 * 66];
    __shared__ float2 sW2[2][576];    // duplicated weights: slot i = (w_i, w_i)

    const int rr0 = tid / 66, cc0 = tid % 66;
    const int yy0 = y0 - 1 + rr0, xx0 = cc0 - 1;
    const bool vi0 = (yy0 >= 0 && yy0 < Hh && xx0 >= 0 && xx0 < Ww);
    const int t1 = tid + 256;
    const int rr1 = t1 / 66, cc1 = t1 % 66;
    const int yy1 = y0 - 1 + rr1, xx1 = cc1 - 1;
    const bool has1 = (t1 < 264);
    const bool vi1 = has1 && (yy1 >= 0 && yy1 < Hh && xx1 >= 0 && xx1 < Ww);

    u64t acc2[8][2];
#pragma unroll
    for (int j = 0; j < 8; j++) { acc2[j][0] = 0ull; acc2[j][1] = 0ull; }

    float pi0, pi1, pw0, pw1, pw2;

#define LOADC(c) { \
    const float* plane = ((c) < 128) ? (inA + (c) * HW) : (inB + ((c) - 128) * HW); \
    pi0 = vi0 ? plane[yy0 * Ww + xx0] : 0.f; \
    pi1 = vi1 ? plane[yy1 * Ww + xx1] : 0.f; \
    const float* wp = wT + ((c) * 128 + ocBase) * 9; \
    pw0 = wp[tid]; pw1 = wp[tid + 256]; \
    pw2 = (tid < 64) ? wp[tid + 512] : 0.f; }

#define STOREC(b) { \
    sIn[b][tid] = pi0; \
    if (has1) sIn[b][t1] = pi1; \
    sW2[b][tid] = make_float2(pw0, pw0); \
    sW2[b][tid + 256] = make_float2(pw1, pw1); \
    if (tid < 64) sW2[b][tid + 512] = make_float2(pw2, pw2); }

    LOADC(c0);
    STOREC(0);
    __syncthreads();

    for (int c = c0; c < c1; c++) {
        const int b = (c - c0) & 1;
        const bool more = (c + 1 < c1);
        if (more) LOADC(c + 1);

        float vin[3][6];
#pragma unroll
        for (int dy = 0; dy < 3; dy++)
#pragma unroll
            for (int j = 0; j < 6; j++)
                vin[dy][j] = sIn[b][(r + dy) * 66 + x4 + j];

        u64t vp[3][5];
#pragma unroll
        for (int dy = 0; dy < 3; dy++)
#pragma unroll
            for (int s = 0; s < 5; s++)
                vp[dy][s] = pk2(vin[dy][s], vin[dy][s + 1]);

#pragma unroll
        for (int j = 0; j < 8; j++) {
            const u64t* wrow = (const u64t*)&sW2[b][(ocg * 8 + j) * 9];
            u64t a0 = acc2[j][0];
            u64t a1 = acc2[j][1];
#pragma unroll
            for (int dy = 0; dy < 3; dy++) {
                u64t w0 = wrow[dy * 3 + 0];
                u64t w1 = wrow[dy * 3 + 1];
                u64t w2 = wrow[dy * 3 + 2];
                a0 = ffma2(vp[dy][0], w0, a0);
                a0 = ffma2(vp[dy][1], w1, a0);
                a0 = ffma2(vp[dy][2], w2, a0);
                a1 = ffma2(vp[dy][2], w0, a1);
                a1 = ffma2(vp[dy][3], w1, a1);
                a1 = ffma2(vp[dy][4], w2, a1);
            }
            acc2[j][0] = a0;
            acc2[j][1] = a1;
        }
        if (more) STOREC(b ^ 1);
        __syncthreads();
    }
#undef LOADC
#undef STOREC

#pragma unroll
    for (int j = 0; j < 8; j++) {
        int oc = ocBase + ocg * 8 + j;
        float4 o;
        upk2(acc2[j][0], o.x, o.y);
        upk2(acc2[j][1], o.z, o.w);
        *(float4*)&outP[oc * HW + (y0 + r) * Ww + x4] = o;
    }
}

// combine z (pA) and r (pB): zg = sigmoid(z), rgh = sigmoid(r) * h
__global__ void k_comb_zr(const float* __restrict__ bz, const float* __restrict__ br) {
    int i = blockIdx.x * 256 + threadIdx.x;
    int oc = i / HW;
    float z = g_pA[i] + g_pA[i + HIDDEN * HW] + g_pA[i + 2 * HIDDEN * HW] + bz[oc];
    z = 1.f / (1.f + expf(-z));
    float rr = g_pB[i] + g_pB[i + HIDDEN * HW] + g_pB[i + 2 * HIDDEN * HW] + br[oc];
    rr = 1.f / (1.f + expf(-rr));
    g_zg[i] = z;
    g_rgh[i] = rr * g_h[i];
}

// combine q (pA): qg = tanh(q); h = (1-z)h + z*qg; zero g_feat
__global__ void k_comb_q(const float* __restrict__ bq) {
    int i = blockIdx.x * 256 + threadIdx.x;
    int oc = i / HW;
    float q = g_pA[i] + g_pA[i + HIDDEN * HW] + g_pA[i + 2 * HIDDEN * HW] + bq[oc];
    q = tanhf(q);
    float z = g_zg[i];
    g_h[i] = (1.f - z) * g_h[i] + z * q;
    if (i < HIDDEN) g_feat[i] = 0.f;
}

// combine h-conv (pB): relu + spatial mean partial -> atomicAdd g_feat
__global__ void k_comb_h(const float* __restrict__ bh) {
    __shared__ float red[256];
    int tid = threadIdx.x;
    int i = blockIdx.x * 256 + tid;
    int oc = i / HW;   // 12 blocks per oc, aligned
    float v = g_pB[i] + g_pB[i + HIDDEN * HW] + g_pB[i + 2 * HIDDEN * HW] + bh[oc];
    v = fmaxf(v, 0.f);
    red[tid] = v;
    __syncthreads();
    for (int s = 128; s > 0; s >>= 1) {
        if (tid < s) red[tid] += red[tid + s];
        __syncthreads();
    }
    if (tid == 0) atomicAdd(&g_feat[oc], red[0]);
}

__global__ void k_pose(const float* __restrict__ Wfc, const float* __restrict__ bfc,
                       float* __restrict__ outp, int writeOut) {
    __shared__ float red[128];
    __shared__ float sdelta[7];
    int t = threadIdx.x;
    float fm = g_feat[t] * (1.0f / 3072.0f);
    for (int j = 0; j < 7; j++) {
        red[t] = fm * Wfc[t * 7 + j];
        __syncthreads();
        for (int s = 64; s > 0; s >>= 1) {
            if (t < s) red[t] += red[t + s];
            __syncthreads();
        }
        if (t == 0) sdelta[j] = 0.01f * (red[0] + bfc[j]);
        __syncthreads();
    }
    if (t == 0) {
        float qc[4] = {g_pose[0], g_pose[1], g_pose[2], g_pose[3]};
        float tc[3] = {g_pose[4], g_pose[5], g_pose[6]};
        float dq[4] = {1.f + sdelta[0], sdelta[1], sdelta[2], sdelta[3]};
        float inv = rsqrtf(dq[0]*dq[0] + dq[1]*dq[1] + dq[2]*dq[2] + dq[3]*dq[3]);
        dq[0] *= inv; dq[1] *= inv; dq[2] *= inv; dq[3] *= inv;
        float dv[3] = {sdelta[4], sdelta[5], sdelta[6]};
        float rv[3];
        qapply_d(qc, dv, rv);
        float tn[3] = {tc[0] + rv[0], tc[1] + rv[1], tc[2] + rv[2]};
        float qn[4];
        qmul_d(qc, dq, qn);
        float inv2 = rsqrtf(qn[0]*qn[0] + qn[1]*qn[1] + qn[2]*qn[2] + qn[3]*qn[3]);
        qn[0] *= inv2; qn[1] *= inv2; qn[2] *= inv2; qn[3] *= inv2;
        g_pose[0] = qn[0]; g_pose[1] = qn[1]; g_pose[2] = qn[2]; g_pose[3] = qn[3];
        g_pose[4] = tn[0]; g_pose[5] = tn[1]; g_pose[6] = tn[2];
        if (writeOut) {
            outp[0] = qn[0]; outp[1] = qn[1]; outp[2] = qn[2]; outp[3] = qn[3];
            outp[4] = tn[0]; outp[5] = tn[1]; outp[6] = tn[2];
        }
    }
}

extern "C" void kernel_launch(void* const* d_in, const int* in_sizes, int n_in,
                              void* d_out, int out_size) {
    const float* fmap_rgb   = (const float*)d_in[0];
    const float* fmap_depth = (const float*)d_in[1];
    const float* depth      = (const float*)d_in[2];
    const float* context    = (const float*)d_in[3];
    const float* intr       = (const float*)d_in[4];
    const float* Wz  = (const float*)d_in[5];
    const float* bz  = (const float*)d_in[6];
    const float* Wr  = (const float*)d_in[7];
    const float* br  = (const float*)d_in[8];
    const float* Wq  = (const float*)d_in[9];
    const float* bq  = (const float*)d_in[10];
    const float* Wh  = (const float*)d_in[11];
    const float* bh  = (const float*)d_in[12];
    const float* Wfc = (const float*)d_in[13];
    const float* bfc = (const float*)d_in[14];
    float* outp = (float*)d_out;

    k_setup<<<12, 256>>>(depth, intr);
    k_zeroh<<<1536, 256>>>();
    k_ctx<<<768, 256>>>(context);
    k_wT<<<2322, 256>>>(Wz, 0);
    k_wT<<<2322, 256>>>(Wr, 1);
    k_wT<<<2322, 256>>>(Wq, 2);
    k_wT<<<576, 256>>>(Wh, 3);

    k_corr<<<dim3(48, 48), 256>>>(fmap_depth, fmap_rgb);
    k_pool<<<9216, 256>>>(1);
    k_pool<<<2304, 256>>>(2);
    k_pool<<<576, 256>>>(3);
    k_sat<<<3072, 128>>>(0);
    k_sat<<<3072, 128>>>(1);
    k_sat<<<3072, 128>>>(2);
    k_sat<<<3072, 128>>>(3);

    dim3 cgrid(2, 24, 3);
    for (int it = 0; it < 4; it++) {
        k_sample_prep<<<1, 64>>>();
        k_conf<<<dim3(37, 4), 256>>>();
        k_topk<<<1, 32>>>();
        k_fused<<<3072, 128>>>();
        k_conv2<<<cgrid, 256>>>(0);
        k_conv2<<<cgrid, 256>>>(1);
        k_comb_zr<<<1536, 256>>>(bz, br);
        k_conv2<<<cgrid, 256>>>(2);
        k_comb_q<<<1536, 256>>>(bq);
        k_conv2<<<cgrid, 256>>>(3);
        k_comb_h<<<1536, 256>>>(bh);
        k_pose<<<1, 128>>>(Wfc, bfc, outp, it == 3 ? 1 : 0);
    }
}

// round 8
// speedup vs baseline: 1.4415x; 1.4415x over previous
#include <cuda_runtime.h>
#include <math.h>

#define Hh 48
#define Ww 64
#define HW 3072
#define Cc 256
#define HIDDEN 128
#define CTX 64
#define CORR_DIM 324
#define GIN 516
#define NSAMP 37
#define SPLITK 6

__constant__ int c_lvlOff[4] = {0, 3072, 3840, 4032};
__constant__ int c_lvlH[4]   = {48, 24, 12, 6};
__constant__ int c_lvlW[4]   = {64, 32, 16, 8};

__constant__ float c_rot[12][3] = {
    {0,0,0},{0,0,0},{0,0,0},{0,0,0},{0,0,0},{0,0,0},
    {1,0,0},{-1,0,0},{0,1,0},{0,-1,0},{0,0,1},{0,0,-1}};
__constant__ float c_trs[12][3] = {
    {1,0,0},{-1,0,0},{0,1,0},{0,-1,0},{0,0,1},{0,0,-1},
    {0,0,0},{0,0,0},{0,0,0},{0,0,0},{0,0,0},{0,0,0}};
__constant__ float c_scales[3] = {0.25f, 1.0f, 4.0f};

__device__ float g_corr[HW * 3072];
__device__ float g_pyr1[HW * 768];
__device__ float g_pyr2[HW * 192];
__device__ float g_pyr3[HW * 48];
__device__ float g_sat0[HW * 3185];
__device__ float g_sat1[HW * 825];
__device__ float g_sat2[HW * 221];
__device__ float g_sat3[HW * 63];
__device__ float g_X[3 * HW];
__device__ float g_K[4];
__device__ float g_samp[NSAMP * 12];
__device__ float g_conf[NSAMP];
__device__ int   g_topi[3];
__device__ float g_wk[3];
__device__ float g_pose[7];
__device__ float g_xin[(CORR_DIM + CTX) * HW];
__device__ float g_h[HIDDEN * HW];
__device__ float g_zg[HIDDEN * HW];
__device__ float g_rgh[HIDDEN * HW];
__device__ float g_feat[HIDDEN];
__device__ float g_pA[SPLITK * HIDDEN * HW];
__device__ float g_pB[SPLITK * HIDDEN * HW];
__device__ float g_wTz[GIN * 128 * 9];
__device__ float g_wTr[GIN * 128 * 9];
__device__ float g_wTq[GIN * 128 * 9];
__device__ float g_wTh[128 * 128 * 9];

// ---- packed fp32x2 helpers (Blackwell dual-rate FP32 path) ----
typedef unsigned long long u64t;
__device__ __forceinline__ u64t pk2(float lo, float hi) {
    u64t r; asm("mov.b64 %0, {%1, %2};" : "=l"(r) : "f"(lo), "f"(hi)); return r;
}
__device__ __forceinline__ void upk2(u64t v, float& lo, float& hi) {
    asm("mov.b64 {%0, %1}, %2;" : "=f"(lo), "=f"(hi) : "l"(v));
}
__device__ __forceinline__ u64t ffma2(u64t a, u64t b, u64t c) {
    u64t d; asm("fma.rn.f32x2 %0, %1, %2, %3;" : "=l"(d) : "l"(a), "l"(b), "l"(c)); return d;
}

__device__ __forceinline__ void qmul_d(const float* a, const float* b, float* o) {
    o[0] = a[0]*b[0] - a[1]*b[1] - a[2]*b[2] - a[3]*b[3];
    o[1] = a[0]*b[1] + a[1]*b[0] + a[2]*b[3] - a[3]*b[2];
    o[2] = a[0]*b[2] - a[1]*b[3] + a[2]*b[0] + a[3]*b[1];
    o[3] = a[0]*b[3] + a[1]*b[2] - a[2]*b[1] + a[3]*b[0];
}
__device__ __forceinline__ void qapply_d(const float* q, const float* v, float* o) {
    float qv[4] = {0.f, v[0], v[1], v[2]};
    float qc[4] = {q[0], -q[1], -q[2], -q[3]};
    float t[4], r[4];
    qmul_d(q, qv, t);
    qmul_d(t, qc, r);
    o[0] = r[1]; o[1] = r[2]; o[2] = r[3];
}

__global__ void k_setup(const float* __restrict__ depth, const float* __restrict__ intr) {
    int p = blockIdx.x * 256 + threadIdx.x;
    float fx = 60.0f + 40.0f * intr[0];
    float fy = 60.0f + 40.0f * intr[1];
    float cx = 32.0f + 4.0f * (intr[2] - 0.5f);
    float cy = 24.0f + 4.0f * (intr[3] - 0.5f);
    if (p == 0) {
        g_K[0] = fx; g_K[1] = fy; g_K[2] = cx; g_K[3] = cy;
        g_pose[0] = 1.f; g_pose[1] = 0.f; g_pose[2] = 0.f; g_pose[3] = 0.f;
        g_pose[4] = 0.f; g_pose[5] = 0.f; g_pose[6] = 0.f;
    }
    if (p < HW) {
        float u = (float)(p % Ww);
        float v = (float)(p / Ww);
        float d = 4.0f + 20.0f * depth[p];
        g_X[p]          = (u - cx) / fx * d;
        g_X[HW + p]     = (v - cy) / fy * d;
        g_X[2 * HW + p] = d;
    }
}

__global__ void k_zeroh() {
    int i = blockIdx.x * 256 + threadIdx.x;
    if (i < HIDDEN * HW) g_h[i] = 0.f;
}

__global__ void k_ctx(const float* __restrict__ ctx) {
    int i = blockIdx.x * 256 + threadIdx.x;
    if (i < CTX * HW) g_xin[CORR_DIM * HW + i] = ctx[i];
}

// corr[i][j] = (1/16) sum_c fd[c][i] * rgb[c][j]
__global__ void k_corr(const float* __restrict__ A, const float* __restrict__ B) {
    __shared__ float As[16][64];
    __shared__ float Bs[16][64];
    int i0 = blockIdx.y * 64;
    int j0 = blockIdx.x * 64;
    int tid = threadIdx.x;
    int tx = tid & 15;
    int ty = tid >> 4;
    float acc[4][4];
#pragma unroll
    for (int r = 0; r < 4; r++)
#pragma unroll
        for (int c = 0; c < 4; c++) acc[r][c] = 0.f;

    for (int k0 = 0; k0 < Cc; k0 += 16) {
        for (int t = tid; t < 1024; t += 256) {
            int kk = t >> 6, ii = t & 63;
            As[kk][ii] = A[(k0 + kk) * HW + i0 + ii];
            Bs[kk][ii] = B[(k0 + kk) * HW + j0 + ii];
        }
        __syncthreads();
#pragma unroll
        for (int kk = 0; kk < 16; kk++) {
            float4 a4 = *(const float4*)&As[kk][ty * 4];
            float4 b4 = *(const float4*)&Bs[kk][tx * 4];
            float a[4] = {a4.x, a4.y, a4.z, a4.w};
            float b[4] = {b4.x, b4.y, b4.z, b4.w};
#pragma unroll
            for (int r = 0; r < 4; r++)
#pragma unroll
                for (int c = 0; c < 4; c++)
                    acc[r][c] = fmaf(a[r], b[c], acc[r][c]);
        }
        __syncthreads();
    }
#pragma unroll
    for (int r = 0; r < 4; r++) {
        float4 o;
        o.x = acc[r][0] * 0.0625f;
        o.y = acc[r][1] * 0.0625f;
        o.z = acc[r][2] * 0.0625f;
        o.w = acc[r][3] * 0.0625f;
        *(float4*)&g_corr[(i0 + ty * 4 + r) * 3072 + j0 + tx * 4] = o;
    }
}

__global__ void k_pool(int level) {
    const float* src; float* dst; int Hs, Ws;
    if (level == 1)      { src = g_corr; dst = g_pyr1; Hs = 48; Ws = 64; }
    else if (level == 2) { src = g_pyr1; dst = g_pyr2; Hs = 24; Ws = 32; }
    else                 { src = g_pyr2; dst = g_pyr3; Hs = 12; Ws = 16; }
    int Hd = Hs >> 1, Wd = Ws >> 1;
    int per = Hd * Wd;
    long idx = (long)blockIdx.x * 256 + threadIdx.x;
    if (idx >= (long)HW * per) return;
    int p = (int)(idx / per), r = (int)(idx % per);
    int hy = r / Wd, wx = r % Wd;
    const float* s = src + (long)p * (Hs * Ws);
    int b = (2 * hy) * Ws + 2 * wx;
    dst[idx] = 0.25f * (s[b] + s[b + 1] + s[b + Ws] + s[b + Ws + 1]);
}

__global__ void k_sat(int level) {
    const float* src; float* dstA; int Hl, Wl;
    if (level == 0)      { src = g_corr; dstA = g_sat0; Hl = 48; Wl = 64; }
    else if (level == 1) { src = g_pyr1; dstA = g_sat1; Hl = 24; Wl = 32; }
    else if (level == 2) { src = g_pyr2; dstA = g_sat2; Hl = 12; Wl = 16; }
    else                 { src = g_pyr3; dstA = g_sat3; Hl = 6;  Wl = 8;  }
    __shared__ float S[3185];
    int p = blockIdx.x;
    int satW = Wl + 1;
    int total = (Hl + 1) * satW;
    const float* s = src + (long)p * (Hl * Wl);
    int t = threadIdx.x;
    for (int c = t; c < satW; c += 128) S[c] = 0.f;
    if (t < Hl) {
        float run = 0.f;
        S[(t + 1) * satW] = 0.f;
        for (int c = 0; c < Wl; c++) {
            run += s[t * Wl + c];
            S[(t + 1) * satW + c + 1] = run;
        }
    }
    __syncthreads();
    if (t >= 1 && t <= Wl) {
        float run = 0.f;
        for (int r = 1; r <= Hl; r++) {
            run += S[r * satW + t];
            S[r * satW + t] = run;
        }
    }
    __syncthreads();
    float* D = dstA + (long)p * total;
    for (int i = t; i < total; i += 128) D[i] = S[i];
}

// W[O][I][9] -> wT[I][O][9]
__global__ void k_wT(const float* __restrict__ w, int which) {
    float* dst; int I;
    if (which == 0)      { dst = g_wTz; I = GIN; }
    else if (which == 1) { dst = g_wTr; I = GIN; }
    else if (which == 2) { dst = g_wTq; I = GIN; }
    else                 { dst = g_wTh; I = 128; }
    int total = 128 * I * 9;
    int idx = blockIdx.x * 256 + threadIdx.x;
    if (idx >= total) return;
    int o = idx / (I * 9);
    int r = idx % (I * 9);
    int i = r / 9, k = r % 9;
    dst[(i * 128 + o) * 9 + k] = w[idx];
}

__global__ void k_sample_prep() {
    int n = threadIdx.x;
    if (n < NSAMP) g_conf[n] = 0.f;
    if (n >= NSAMP) return;
    float qc[4] = {g_pose[0], g_pose[1], g_pose[2], g_pose[3]};
    float tc[3] = {g_pose[4], g_pose[5], g_pose[6]};
    float dq[4], dt[3];
    if (n < 36) {
        int b = n / 3, m = n % 3;
        float sc = c_scales[m];
        float rx = c_rot[b][0], ry = c_rot[b][1], rz = c_rot[b][2];
        float rn = sqrtf(rx * rx + ry * ry + rz * rz);
        float dnm = fmaxf(rn, 1e-8f);
        float ha = 0.02f * sc * 0.5f;
        float sh = sinf(ha);
        dq[0] = cosf(ha);
        dq[1] = rx / dnm * sh;
        dq[2] = ry / dnm * sh;
        dq[3] = rz / dnm * sh;
        float ts = 0.02f * sc;
        dt[0] = c_trs[b][0] * ts;
        dt[1] = c_trs[b][1] * ts;
        dt[2] = c_trs[b][2] * ts;
    } else {
        dq[0] = 1.f; dq[1] = 0.f; dq[2] = 0.f; dq[3] = 0.f;
        dt[0] = 0.f; dt[1] = 0.f; dt[2] = 0.f;
    }
    float q[4];
    qmul_d(qc, dq, q);
    float inv = rsqrtf(q[0]*q[0] + q[1]*q[1] + q[2]*q[2] + q[3]*q[3]);
    q[0] *= inv; q[1] *= inv; q[2] *= inv; q[3] *= inv;
    float rd[3];
    qapply_d(qc, dt, rd);
    float w = q[0], x = q[1], y = q[2], z = q[3];
    float* S = g_samp + n * 12;
    S[0] = 1.f - 2.f * (y * y + z * z);
    S[1] = 2.f * (x * y - w * z);
    S[2] = 2.f * (x * z + w * y);
    S[3] = 2.f * (x * y + w * z);
    S[4] = 1.f - 2.f * (x * x + z * z);
    S[5] = 2.f * (y * z - w * x);
    S[6] = 2.f * (x * z - w * y);
    S[7] = 2.f * (y * z + w * x);
    S[8] = 1.f - 2.f * (x * x + y * y);
    S[9]  = tc[0] + rd[0];
    S[10] = tc[1] + rd[1];
    S[11] = tc[2] + rd[2];
}

__device__ __forceinline__ float satT(const float* S, int Hl, int Wl, int satW, int a, int b) {
    int c0 = min(max(a - 4, 0), Wl);
    int c1 = min(max(a + 5, 0), Wl);
    int r0 = min(max(b - 4, 0), Hl);
    int r1 = min(max(b + 5, 0), Hl);
    return S[r1 * satW + c1] - S[r0 * satW + c1] - S[r1 * satW + c0] + S[r0 * satW + c0];
}

__device__ __forceinline__ float confLevel(const float* S, int Hl, int Wl, int satW,
                                           float ul, float vl) {
    float bx = floorf(ul), by = floorf(vl);
    float fx = ul - bx, fy = vl - by;
    int ax = (int)bx, ay = (int)by;
    float T00 = satT(S, Hl, Wl, satW, ax,     ay);
    float T10 = satT(S, Hl, Wl, satW, ax + 1, ay);
    float T01 = satT(S, Hl, Wl, satW, ax,     ay + 1);
    float T11 = satT(S, Hl, Wl, satW, ax + 1, ay + 1);
    return (1.f - fx) * (1.f - fy) * T00 + fx * (1.f - fy) * T10
         + (1.f - fx) * fy * T01 + fx * fy * T11;
}

__global__ void k_conf() {
    int n = blockIdx.x;
    int chunk = blockIdx.y;           // 0..3, 768 px each
    __shared__ float sR[12];
    __shared__ float red[256];
    int tid = threadIdx.x;
    if (tid < 12) sR[tid] = g_samp[n * 12 + tid];
    __syncthreads();
    float fx = g_K[0], fy = g_K[1], cx = g_K[2], cy = g_K[3];
    float acc = 0.f;
    int p0 = chunk * 768;
    for (int p = p0 + tid; p < p0 + 768; p += 256) {
        float X = g_X[p], Y = g_X[HW + p], Z = g_X[2 * HW + p];
        float xc = sR[0] * X + sR[1] * Y + sR[2] * Z + sR[9];
        float yc = sR[3] * X + sR[4] * Y + sR[5] * Z + sR[10];
        float zc = sR[6] * X + sR[7] * Y + sR[8] * Z + sR[11];
        zc = fmaxf(zc, 0.1f);
        float u = fx * xc / zc + cx;
        float v = fy * yc / zc + cy;
        acc += confLevel(g_sat0 + (long)p * 3185, 48, 64, 65, u,          v);
        acc += confLevel(g_sat1 + (long)p * 825,  24, 32, 33, u * 0.5f,   v * 0.5f);
        acc += confLevel(g_sat2 + (long)p * 221,  12, 16, 17, u * 0.25f,  v * 0.25f);
        acc += confLevel(g_sat3 + (long)p * 63,    6,  8,  9, u * 0.125f, v * 0.125f);
    }
    red[tid] = acc;
    __syncthreads();
    for (int s = 128; s > 0; s >>= 1) {
        if (tid < s) red[tid] += red[tid + s];
        __syncthreads();
    }
    if (tid == 0) atomicAdd(&g_conf[n], red[0]);
}

__global__ void k_topk() {
    if (threadIdx.x != 0) return;
    float v[NSAMP];
    for (int i = 0; i < NSAMP; i++) v[i] = g_conf[i] * (1.0f / 995328.0f);
    float tv[3]; int ti[3];
    for (int k = 0; k < 3; k++) {
        float best = -1e30f; int bi = 0;
        for (int i = 0; i < NSAMP; i++)
            if (v[i] > best) { best = v[i]; bi = i; }
        tv[k] = best; ti[k] = bi;
        v[bi] = -1e30f;
    }
    float m = tv[0];
    float e0 = expf(tv[0] - m), e1 = expf(tv[1] - m), e2 = expf(tv[2] - m);
    float s = e0 + e1 + e2;
    g_topi[0] = ti[0]; g_topi[1] = ti[1]; g_topi[2] = ti[2];
    g_wk[0] = e0 / s; g_wk[1] = e1 / s; g_wk[2] = e2 / s;
}

// fused correlation features for the top-3 samples -> g_xin planes [0,324)
__global__ void k_fused() {
    int p = blockIdx.x;
    __shared__ float sRow[4080];
    __shared__ int   sBx[12], sBy[12];
    __shared__ float sFx[12], sFy[12], sWk[3];
    int tid = threadIdx.x;
    {
        const float* r0 = g_corr + (long)p * 3072;
        for (int i = tid; i < 3072; i += 128) sRow[i] = r0[i];
        const float* r1 = g_pyr1 + (long)p * 768;
        for (int i = tid; i < 768; i += 128) sRow[3072 + i] = r1[i];
        const float* r2 = g_pyr2 + (long)p * 192;
        for (int i = tid; i < 192; i += 128) sRow[3840 + i] = r2[i];
        const float* r3 = g_pyr3 + (long)p * 48;
        if (tid < 48) sRow[4032 + tid] = r3[tid];
    }
    if (tid < 3) {
        int n = g_topi[tid];
        sWk[tid] = g_wk[tid];
        const float* S = g_samp + n * 12;
        float X = g_X[p], Y = g_X[HW + p], Z = g_X[2 * HW + p];
        float xc = S[0] * X + S[1] * Y + S[2] * Z + S[9];
        float yc = S[3] * X + S[4] * Y + S[5] * Z + S[10];
        float zc = S[6] * X + S[7] * Y + S[8] * Z + S[11];
        zc = fmaxf(zc, 0.1f);
        float u = g_K[0] * xc / zc + g_K[2];
        float v = g_K[1] * yc / zc + g_K[3];
        float inv = 1.f;
        for (int l = 0; l < 4; l++) {
            float ul = u * inv, vl = v * inv;
            float bx = floorf(ul), by = floorf(vl);
            sBx[tid * 4 + l] = (int)bx;
            sBy[tid * 4 + l] = (int)by;
            sFx[tid * 4 + l] = ul - bx;
            sFy[tid * 4 + l] = vl - by;
            inv *= 0.5f;
        }
    }
    __syncthreads();
    for (int c = tid; c < CORR_DIM; c += 128) {
        int l = c / 81, o = c % 81;
        int oy = o / 9 - 4, ox = o % 9 - 4;
        const float* row = sRow + c_lvlOff[l];
        int Hl = c_lvlH[l], Wl = c_lvlW[l];
        float acc = 0.f;
#pragma unroll
        for (int k = 0; k < 3; k++) {
            int i = k * 4 + l;
            int x0 = sBx[i] + ox, y0 = sBy[i] + oy;
            float fxw = sFx[i], fyw = sFy[i];
            float s = 0.f;
            bool vx0 = (x0 >= 0 && x0 < Wl);
            bool vx1 = (x0 + 1 >= 0 && x0 + 1 < Wl);
            bool vy0 = (y0 >= 0 && y0 < Hl);
            bool vy1 = (y0 + 1 >= 0 && y0 + 1 < Hl);
            if (vx0 && vy0) s += (1.f - fxw) * (1.f - fyw) * row[y0 * Wl + x0];
            if (vx1 && vy0) s += fxw * (1.f - fyw) * row[y0 * Wl + x0 + 1];
            if (vx0 && vy1) s += (1.f - fxw) * fyw * row[(y0 + 1) * Wl + x0];
            if (vx1 && vy1) s += fxw * fyw * row[(y0 + 1) * Wl + x0 + 1];
            acc += sWk[k] * s;
        }
        g_xin[c * HW + p] = acc;
    }
}

// ---------------------------------------------------------------------------
// Conv v4: implicit GEMM, FFMA2 with dy-outer loop (small live set),
// tile 64 oc x 128 px, splitK=6, double-buffered smem, duplicated weights
// so a broadcast LDS.64 yields the packed (w,w) operand.
// ---------------------------------------------------------------------------
__global__ void __launch_bounds__(256) k_conv2(int mode) {
    const float* inA; const float* inB; const float* wT; float* outP; int C;
    if (mode == 0)      { inA = g_h;   inB = g_xin; wT = g_wTz; outP = g_pA; C = GIN; }
    else if (mode == 1) { inA = g_h;   inB = g_xin; wT = g_wTr; outP = g_pB; C = GIN; }
    else if (mode == 2) { inA = g_rgh; inB = g_xin; wT = g_wTq; outP = g_pA; C = GIN; }
    else                { inA = g_h;   inB = g_h;   wT = g_wTh; outP = g_pB; C = 128; }

    const int y0 = blockIdx.y * 2;
    const int ocBase = blockIdx.x * 64;
    const int kz = blockIdx.z;
    const int c0 = kz * C / SPLITK;
    const int c1 = (kz + 1) * C / SPLITK;
    outP += kz * HIDDEN * HW;

    const int tid = threadIdx.x;
    const int pxg = tid & 31;
    const int ocg = tid >> 5;
    const int r  = pxg >> 4;          // 0..1 output row within tile
    const int x4 = (pxg & 15) * 4;    // 0,4,...,60

    __shared__ float  sIn[2][4 * 66];
    __shared__ float2 sW2[2][576];    // duplicated weights: slot i = (w_i, w_i)

    const int rr0 = tid / 66, cc0 = tid % 66;
    const int yy0 = y0 - 1 + rr0, xx0 = cc0 - 1;
    const bool vi0 = (yy0 >= 0 && yy0 < Hh && xx0 >= 0 && xx0 < Ww);
    const int t1 = tid + 256;
    const int rr1 = t1 / 66, cc1 = t1 % 66;
    const int yy1 = y0 - 1 + rr1, xx1 = cc1 - 1;
    const bool has1 = (t1 < 264);
    const bool vi1 = has1 && (yy1 >= 0 && yy1 < Hh && xx1 >= 0 && xx1 < Ww);

    u64t acc2[8][2];
#pragma unroll
    for (int j = 0; j < 8; j++) { acc2[j][0] = 0ull; acc2[j][1] = 0ull; }

    float pi0, pi1, pw0, pw1, pw2;

#define LOADC(c) { \
    const float* plane = ((c) < 128) ? (inA + (c) * HW) : (inB + ((c) - 128) * HW); \
    pi0 = vi0 ? plane[yy0 * Ww + xx0] : 0.f; \
    pi1 = vi1 ? plane[yy1 * Ww + xx1] : 0.f; \
    const float* wp = wT + ((c) * 128 + ocBase) * 9; \
    pw0 = wp[tid]; pw1 = wp[tid + 256]; \
    pw2 = (tid < 64) ? wp[tid + 512] : 0.f; }

#define STOREC(b) { \
    sIn[b][tid] = pi0; \
    if (has1) sIn[b][t1] = pi1; \
    sW2[b][tid] = make_float2(pw0, pw0); \
    sW2[b][tid + 256] = make_float2(pw1, pw1); \
    if (tid < 64) sW2[b][tid + 512] = make_float2(pw2, pw2); }

    LOADC(c0);
    STOREC(0);
    __syncthreads();

    for (int c = c0; c < c1; c++) {
        const int b = (c - c0) & 1;
        const bool more = (c + 1 < c1);
        if (more) LOADC(c + 1);

#pragma unroll
        for (int dy = 0; dy < 3; dy++) {
            const float* inrow = &sIn[b][(r + dy) * 66 + x4];
            float v0 = inrow[0], v1 = inrow[1], v2 = inrow[2];
            float v3 = inrow[3], v4 = inrow[4], v5 = inrow[5];
            u64t p0 = pk2(v0, v1);
            u64t p1 = pk2(v1, v2);
            u64t p2 = pk2(v2, v3);
            u64t p3 = pk2(v3, v4);
            u64t p4 = pk2(v4, v5);
            const u64t* wbase = (const u64t*)&sW2[b][ocg * 72 + dy * 3];
#pragma unroll
            for (int j = 0; j < 8; j++) {
                u64t w0 = wbase[j * 9 + 0];
                u64t w1 = wbase[j * 9 + 1];
                u64t w2 = wbase[j * 9 + 2];
                acc2[j][0] = ffma2(p0, w0, ffma2(p1, w1, ffma2(p2, w2, acc2[j][0])));
                acc2[j][1] = ffma2(p2, w0, ffma2(p3, w1, ffma2(p4, w2, acc2[j][1])));
            }
        }
        if (more) STOREC(b ^ 1);
        __syncthreads();
    }
#undef LOADC
#undef STOREC

#pragma unroll
    for (int j = 0; j < 8; j++) {
        int oc = ocBase + ocg * 8 + j;
        float4 o;
        upk2(acc2[j][0], o.x, o.y);
        upk2(acc2[j][1], o.z, o.w);
        *(float4*)&outP[oc * HW + (y0 + r) * Ww + x4] = o;
    }
}

__device__ __forceinline__ float sum6(const float* P, int i) {
    float s = P[i];
#pragma unroll
    for (int k = 1; k < SPLITK; k++) s += P[i + k * HIDDEN * HW];
    return s;
}

// combine z (pA) and r (pB): zg = sigmoid(z), rgh = sigmoid(r) * h
__global__ void k_comb_zr(const float* __restrict__ bz, const float* __restrict__ br) {
    int i = blockIdx.x * 256 + threadIdx.x;
    int oc = i / HW;
    float z = sum6(g_pA, i) + bz[oc];
    z = 1.f / (1.f + expf(-z));
    float rr = sum6(g_pB, i) + br[oc];
    rr = 1.f / (1.f + expf(-rr));
    g_zg[i] = z;
    g_rgh[i] = rr * g_h[i];
}

// combine q (pA): qg = tanh(q); h = (1-z)h + z*qg; zero g_feat
__global__ void k_comb_q(const float* __restrict__ bq) {
    int i = blockIdx.x * 256 + threadIdx.x;
    int oc = i / HW;
    float q = sum6(g_pA, i) + bq[oc];
    q = tanhf(q);
    float z = g_zg[i];
    g_h[i] = (1.f - z) * g_h[i] + z * q;
    if (i < HIDDEN) g_feat[i] = 0.f;
}

// combine h-conv (pB): relu + spatial mean partial -> atomicAdd g_feat
__global__ void k_comb_h(const float* __restrict__ bh) {
    __shared__ float red[256];
    int tid = threadIdx.x;
    int i = blockIdx.x * 256 + tid;
    int oc = i / HW;   // 12 blocks per oc, aligned
    float v = sum6(g_pB, i) + bh[oc];
    v = fmaxf(v, 0.f);
    red[tid] = v;
    __syncthreads();
    for (int s = 128; s > 0; s >>= 1) {
        if (tid < s) red[tid] += red[tid + s];
        __syncthreads();
    }
    if (tid == 0) atomicAdd(&g_feat[oc], red[0]);
}

__global__ void k_pose(const float* __restrict__ Wfc, const float* __restrict__ bfc,
                       float* __restrict__ outp, int writeOut) {
    __shared__ float red[128];
    __shared__ float sdelta[7];
    int t = threadIdx.x;
    float fm = g_feat[t] * (1.0f / 3072.0f);
    for (int j = 0; j < 7; j++) {
        red[t] = fm * Wfc[t * 7 + j];
        __syncthreads();
        for (int s = 64; s > 0; s >>= 1) {
            if (t < s) red[t] += red[t + s];
            __syncthreads();
        }
        if (t == 0) sdelta[j] = 0.01f * (red[0] + bfc[j]);
        __syncthreads();
    }
    if (t == 0) {
        float qc[4] = {g_pose[0], g_pose[1], g_pose[2], g_pose[3]};
        float tc[3] = {g_pose[4], g_pose[5], g_pose[6]};
        float dq[4] = {1.f + sdelta[0], sdelta[1], sdelta[2], sdelta[3]};
        float inv = rsqrtf(dq[0]*dq[0] + dq[1]*dq[1] + dq[2]*dq[2] + dq[3]*dq[3]);
        dq[0] *= inv; dq[1] *= inv; dq[2] *= inv; dq[3] *= inv;
        float dv[3] = {sdelta[4], sdelta[5], sdelta[6]};
        float rv[3];
        qapply_d(qc, dv, rv);
        float tn[3] = {tc[0] + rv[0], tc[1] + rv[1], tc[2] + rv[2]};
        float qn[4];
        qmul_d(qc, dq, qn);
        float inv2 = rsqrtf(qn[0]*qn[0] + qn[1]*qn[1] + qn[2]*qn[2] + qn[3]*qn[3]);
        qn[0] *= inv2; qn[1] *= inv2; qn[2] *= inv2; qn[3] *= inv2;
        g_pose[0] = qn[0]; g_pose[1] = qn[1]; g_pose[2] = qn[2]; g_pose[3] = qn[3];
        g_pose[4] = tn[0]; g_pose[5] = tn[1]; g_pose[6] = tn[2];
        if (writeOut) {
            outp[0] = qn[0]; outp[1] = qn[1]; outp[2] = qn[2]; outp[3] = qn[3];
            outp[4] = tn[0]; outp[5] = tn[1]; outp[6] = tn[2];
        }
    }
}

extern "C" void kernel_launch(void* const* d_in, const int* in_sizes, int n_in,
                              void* d_out, int out_size) {
    const float* fmap_rgb   = (const float*)d_in[0];
    const float* fmap_depth = (const float*)d_in[1];
    const float* depth      = (const float*)d_in[2];
    const float* context    = (const float*)d_in[3];
    const float* intr       = (const float*)d_in[4];
    const float* Wz  = (const float*)d_in[5];
    const float* bz  = (const float*)d_in[6];
    const float* Wr  = (const float*)d_in[7];
    const float* br  = (const float*)d_in[8];
    const float* Wq  = (const float*)d_in[9];
    const float* bq  = (const float*)d_in[10];
    const float* Wh  = (const float*)d_in[11];
    const float* bh  = (const float*)d_in[12];
    const float* Wfc = (const float*)d_in[13];
    const float* bfc = (const float*)d_in[14];
    float* outp = (float*)d_out;

    k_setup<<<12, 256>>>(depth, intr);
    k_zeroh<<<1536, 256>>>();
    k_ctx<<<768, 256>>>(context);
    k_wT<<<2322, 256>>>(Wz, 0);
    k_wT<<<2322, 256>>>(Wr, 1);
    k_wT<<<2322, 256>>>(Wq, 2);
    k_wT<<<576, 256>>>(Wh, 3);

    k_corr<<<dim3(48, 48), 256>>>(fmap_depth, fmap_rgb);
    k_pool<<<9216, 256>>>(1);
    k_pool<<<2304, 256>>>(2);
    k_pool<<<576, 256>>>(3);
    k_sat<<<3072, 128>>>(0);
    k_sat<<<3072, 128>>>(1);
    k_sat<<<3072, 128>>>(2);
    k_sat<<<3072, 128>>>(3);

    dim3 cgrid(2, 24, SPLITK);
    for (int it = 0; it < 4; it++) {
        k_sample_prep<<<1, 64>>>();
        k_conf<<<dim3(37, 4), 256>>>();
        k_topk<<<1, 32>>>();
        k_fused<<<3072, 128>>>();
        k_conv2<<<cgrid, 256>>>(0);
        k_conv2<<<cgrid, 256>>>(1);
        k_comb_zr<<<1536, 256>>>(bz, br);
        k_conv2<<<cgrid, 256>>>(2);
        k_comb_q<<<1536, 256>>>(bq);
        k_conv2<<<cgrid, 256>>>(3);
        k_comb_h<<<1536, 256>>>(bh);
        k_pose<<<1, 128>>>(Wfc, bfc, outp, it == 3 ? 1 : 0);
    }
}